// round 5
// baseline (speedup 1.0000x reference)
#include <cuda_runtime.h>
#include <cstdint>

// Problem constants
#define BB 8
#define HH 512
#define EE 256
#define TT 2048
#define SS 2048
#define SCALE 0.8366600265340756f  // sqrt(0.7)

// Scratch (device globals — no allocation allowed in kernel_launch)
__device__ float g_Q[BB * TT * EE];    // 16.8 MB
__device__ float g_ctx[BB * TT * EE];  // 16.8 MB
__device__ float g_Vt[BB * EE * SS];   // 16.8 MB (en_combined transposed)

__device__ __forceinline__ float tf32r(float x) {
    uint32_t u;
    asm("cvt.rna.tf32.f32 %0, %1;" : "=r"(u) : "f"(x));
    return __uint_as_float(u);
}
__device__ __forceinline__ void mma8(float* c, const uint32_t* a, const uint32_t* b) {
    asm volatile("mma.sync.aligned.m16n8k8.row.col.f32.tf32.tf32.f32 "
        "{%0,%1,%2,%3}, {%4,%5,%6,%7}, {%8,%9}, {%0,%1,%2,%3};"
        : "+f"(c[0]), "+f"(c[1]), "+f"(c[2]), "+f"(c[3])
        : "r"(a[0]), "r"(a[1]), "r"(a[2]), "r"(a[3]), "r"(b[0]), "r"(b[1]));
}
#define FU(x) __float_as_uint(x)
__device__ __forceinline__ uint32_t smem_u32(const void* p) {
    uint32_t a;
    asm("{ .reg .u64 t; cvta.to.shared.u64 t, %1; cvt.u32.u64 %0, t; }" : "=r"(a) : "l"(p));
    return a;
}
#define CPA16(dst, src) \
    asm volatile("cp.async.ca.shared.global [%0], [%1], 16;" :: "r"(dst), "l"(src))
#define CPA_COMMIT() asm volatile("cp.async.commit_group;" ::: "memory")
#define CPA_WAIT(n)  asm volatile("cp.async.wait_group %0;" :: "n"(n) : "memory")

// ==================== 3xTF32 GEMM: C[128,128] tile, cp.async pipelined ====================
// C[m,n] = sum_k A[m,k] * B[n,k]  (both K-major). Raw fp32 tiles in SMEM,
// hi/lo split at fragment-read time. 256 thr = 8 warps (2x4), warp tile 64x32.
#define QP 36                             // SMEM row pitch (floats): conflict-free
#define STAGE_F (2 * 128 * QP)            // A tile + B tile per stage (floats)
#define GEMM_SMEM (2 * STAGE_F * 4)       // 2 stages = 73728 B

__global__ void __launch_bounds__(256, 2) gemm3x(
    const float* __restrict__ A, int lda, size_t sA,
    const float* __restrict__ B, int ldb, size_t sB,
    float* __restrict__ C, int ldc, size_t sC, int K)
{
    extern __shared__ float sm[];

    const int tid  = threadIdx.x;
    const int lane = tid & 31;
    const int wid  = tid >> 5;
    const int mB   = (wid >> 2) * 64;   // warp row base (2 rows of warps)
    const int nB   = (wid & 3) * 32;    // warp col base (4 cols of warps)
    const int g    = lane >> 2;         // groupID 0..7
    const int tg   = lane & 3;          // 0..3

    const int ldr = tid >> 3;           // 0..31
    const int ldk = (tid & 7) << 2;     // 0,4,...,28

    const float* Ab = A + blockIdx.z * sA + (size_t)(blockIdx.y * 128) * lda;
    const float* Bb = B + blockIdx.z * sB + (size_t)(blockIdx.x * 128) * ldb;

    const uint32_t smb = smem_u32(sm);
    const int NC = K >> 5;

    float acc[4][4][4] = {};  // [mi][ni][reg]

    // ---- issue stage 0 ----
    {
        const uint32_t sa = smb;                      // A tile stage 0
        const uint32_t sb = smb + 128 * QP * 4;       // B tile stage 0
#pragma unroll
        for (int p = 0; p < 4; p++) {
            const int row = p * 32 + ldr;
            CPA16(sa + (row * QP + ldk) * 4, Ab + (size_t)row * lda + ldk);
            CPA16(sb + (row * QP + ldk) * 4, Bb + (size_t)row * ldb + ldk);
        }
        CPA_COMMIT();
    }

    for (int c = 0; c < NC; c++) {
        // prefetch stage c+1 into buffer (c+1)&1 (safe: its readers finished at end of iter c-1)
        if (c + 1 < NC) {
            const int k1 = (c + 1) << 5;
            const uint32_t base = smb + ((c + 1) & 1) * STAGE_F * 4;
            const uint32_t sa = base;
            const uint32_t sb = base + 128 * QP * 4;
#pragma unroll
            for (int p = 0; p < 4; p++) {
                const int row = p * 32 + ldr;
                CPA16(sa + (row * QP + ldk) * 4, Ab + (size_t)row * lda + k1 + ldk);
                CPA16(sb + (row * QP + ldk) * 4, Bb + (size_t)row * ldb + k1 + ldk);
            }
            CPA_COMMIT();
            CPA_WAIT(1);
        } else {
            CPA_WAIT(0);
        }
        __syncthreads();

        const float* As = sm + (c & 1) * STAGE_F;
        const float* Bs = As + 128 * QP;

#pragma unroll
        for (int ks = 0; ks < 4; ks++) {
            const int kc = ks * 8 + tg;
            uint32_t ah[4][4], al[4][4];
#pragma unroll
            for (int mi = 0; mi < 4; mi++) {
                const int r0 = (mB + mi * 16 + g) * QP;
                const int r1 = r0 + 8 * QP;
                float x;
                x = As[r0 + kc];     ah[mi][0] = FU(tf32r(x)); al[mi][0] = FU(tf32r(x - __uint_as_float(ah[mi][0])));
                x = As[r1 + kc];     ah[mi][1] = FU(tf32r(x)); al[mi][1] = FU(tf32r(x - __uint_as_float(ah[mi][1])));
                x = As[r0 + kc + 4]; ah[mi][2] = FU(tf32r(x)); al[mi][2] = FU(tf32r(x - __uint_as_float(ah[mi][2])));
                x = As[r1 + kc + 4]; ah[mi][3] = FU(tf32r(x)); al[mi][3] = FU(tf32r(x - __uint_as_float(ah[mi][3])));
            }
            uint32_t bh[4][2], bl[4][2];
#pragma unroll
            for (int ni = 0; ni < 4; ni++) {
                const int n0 = (nB + ni * 8 + g) * QP;
                float x;
                x = Bs[n0 + kc];     bh[ni][0] = FU(tf32r(x)); bl[ni][0] = FU(tf32r(x - __uint_as_float(bh[ni][0])));
                x = Bs[n0 + kc + 4]; bh[ni][1] = FU(tf32r(x)); bl[ni][1] = FU(tf32r(x - __uint_as_float(bh[ni][1])));
            }
#pragma unroll
            for (int mi = 0; mi < 4; mi++)
#pragma unroll
                for (int ni = 0; ni < 4; ni++) {
                    mma8(acc[mi][ni], ah[mi], bh[ni]);
                    mma8(acc[mi][ni], ah[mi], bl[ni]);
                    mma8(acc[mi][ni], al[mi], bh[ni]);
                }
        }
        __syncthreads();
    }

    // ---- epilogue ----
    float* Cb = C + blockIdx.z * sC;
#pragma unroll
    for (int mi = 0; mi < 4; mi++) {
        const int r0 = blockIdx.y * 128 + mB + mi * 16 + g;
#pragma unroll
        for (int ni = 0; ni < 4; ni++) {
            const int cc = blockIdx.x * 128 + nB + ni * 8 + 2 * tg;
            float2 v0 = {acc[mi][ni][0], acc[mi][ni][1]};
            float2 v1 = {acc[mi][ni][2], acc[mi][ni][3]};
            *(float2*)(Cb + (size_t)r0 * ldc + cc) = v0;
            *(float2*)(Cb + (size_t)(r0 + 8) * ldc + cc) = v1;
        }
    }
}

// ==================== K0: transpose V[b,s,e] -> Vt[b,e,s] ====================
__global__ void __launch_bounds__(256) k0_transpose(
    const float* __restrict__ V, float* __restrict__ Vt)
{
    __shared__ float t[32][33];
    const int b = blockIdx.z;
    const int s0 = blockIdx.x * 32, e0 = blockIdx.y * 32;
    const float* Vb = V + (size_t)b * SS * EE;
    float* Vtb = Vt + (size_t)b * EE * SS;
    const int x = threadIdx.x, y = threadIdx.y;
#pragma unroll
    for (int i = 0; i < 32; i += 8)
        t[y + i][x] = Vb[(size_t)(s0 + y + i) * EE + e0 + x];
    __syncthreads();
#pragma unroll
    for (int i = 0; i < 32; i += 8)
        Vtb[(size_t)(e0 + y + i) * SS + s0 + x] = t[x][y + i];
}

// ==================== K1: Q projection (SIMT fp32) ====================
__global__ void __launch_bounds__(256) k1_q(
    const float* __restrict__ dec,   // [B,H,T]
    const float* __restrict__ emb,   // [B,T,E]
    const float* __restrict__ W,     // [E,H]
    const float* __restrict__ bias)  // [E]
{
    __shared__ float As[8][128];
    __shared__ float Bs[8][128];
    const int b  = blockIdx.z;
    const int tB = blockIdx.y * 128;
    const int eB = blockIdx.x * 128;
    const int tid = threadIdx.x;
    const int m0 = (tid >> 4) << 3;
    const int n0 = (tid & 15) << 3;
    const int a_h = tid >> 5;
    const int a_t = (tid & 31) << 2;
    const int b_e = tid >> 1;
    const int b_h = (tid & 1) << 2;
    const float* Ag = dec + (size_t)b * HH * TT;
    float acc[8][8] = {};
    for (int k0 = 0; k0 < HH; k0 += 8) {
        float4 av = *(const float4*)(Ag + (size_t)(k0 + a_h) * TT + tB + a_t);
        *(float4*)&As[a_h][a_t] = av;
        float4 bv = *(const float4*)(W + (size_t)(eB + b_e) * HH + k0 + b_h);
        Bs[b_h + 0][b_e] = bv.x; Bs[b_h + 1][b_e] = bv.y;
        Bs[b_h + 2][b_e] = bv.z; Bs[b_h + 3][b_e] = bv.w;
        __syncthreads();
#pragma unroll
        for (int k = 0; k < 8; k++) {
            float a[8], bb[8];
            *(float4*)&a[0]  = *(const float4*)&As[k][m0];
            *(float4*)&a[4]  = *(const float4*)&As[k][m0 + 4];
            *(float4*)&bb[0] = *(const float4*)&Bs[k][n0];
            *(float4*)&bb[4] = *(const float4*)&Bs[k][n0 + 4];
#pragma unroll
            for (int i = 0; i < 8; i++)
#pragma unroll
                for (int j = 0; j < 8; j++) acc[i][j] = fmaf(a[i], bb[j], acc[i][j]);
        }
        __syncthreads();
    }
#pragma unroll
    for (int i = 0; i < 8; i++) {
        const size_t rowo = ((size_t)b * TT + tB + m0 + i) * EE;
#pragma unroll
        for (int j = 0; j < 8; j += 4) {
            const int e = eB + n0 + j;
            float4 ev = *(const float4*)(emb + rowo + e);
            float4 bi = *(const float4*)(bias + e);
            float4 o;
            o.x = SCALE * (acc[i][j + 0] + bi.x + ev.x);
            o.y = SCALE * (acc[i][j + 1] + bi.y + ev.y);
            o.z = SCALE * (acc[i][j + 2] + bi.z + ev.z);
            o.w = SCALE * (acc[i][j + 3] + bi.w + ev.w);
            *(float4*)(g_Q + rowo + e) = o;
        }
    }
}

// ==================== K3: softmax ====================
__global__ void __launch_bounds__(256) k3_softmax(float* __restrict__ a)
{
    const size_t row = blockIdx.x;
    float* p = a + row * SS;
    const int tid = threadIdx.x;
    float v[8];
#pragma unroll
    for (int i = 0; i < 8; i++) v[i] = p[tid + (i << 8)];
    float m = v[0];
#pragma unroll
    for (int i = 1; i < 8; i++) m = fmaxf(m, v[i]);
#pragma unroll
    for (int o = 16; o > 0; o >>= 1) m = fmaxf(m, __shfl_xor_sync(0xffffffffu, m, o));
    __shared__ float red[8];
    if ((tid & 31) == 0) red[tid >> 5] = m;
    __syncthreads();
    float M = red[0];
#pragma unroll
    for (int i = 1; i < 8; i++) M = fmaxf(M, red[i]);
    float s = 0.f;
#pragma unroll
    for (int i = 0; i < 8; i++) { v[i] = __expf(v[i] - M); s += v[i]; }
#pragma unroll
    for (int o = 16; o > 0; o >>= 1) s += __shfl_xor_sync(0xffffffffu, s, o);
    __syncthreads();
    if ((tid & 31) == 0) red[tid >> 5] = s;
    __syncthreads();
    float Z = 0.f;
#pragma unroll
    for (int i = 0; i < 8; i++) Z += red[i];
    const float inv = 1.f / Z;
#pragma unroll
    for (int i = 0; i < 8; i++) p[tid + (i << 8)] = v[i] * inv;
}

// ==================== K5: output projection (SIMT fp32) ====================
__global__ void __launch_bounds__(256) k5_out(
    const float* __restrict__ dec,   // [B,H,T]
    const float* __restrict__ W,     // [H,E]
    const float* __restrict__ bias,  // [H]
    float* __restrict__ out)         // [B,H,T]
{
    __shared__ float As[8][128];
    __shared__ float Bs[8][128];
    const int b  = blockIdx.z;
    const int tB = blockIdx.y * 128;
    const int hB = blockIdx.x * 128;
    const int tid = threadIdx.x;
    const int m0 = (tid >> 4) << 3;
    const int n0 = (tid & 15) << 3;
    const int lr = tid >> 1;
    const int lk = (tid & 1) << 2;
    const float* Ag = g_ctx + (size_t)b * TT * EE;
    float acc[8][8] = {};
    for (int k0 = 0; k0 < EE; k0 += 8) {
        float4 av = *(const float4*)(Ag + (size_t)(tB + lr) * EE + k0 + lk);
        As[lk + 0][lr] = av.x; As[lk + 1][lr] = av.y;
        As[lk + 2][lr] = av.z; As[lk + 3][lr] = av.w;
        float4 bv = *(const float4*)(W + (size_t)(hB + lr) * EE + k0 + lk);
        Bs[lk + 0][lr] = bv.x; Bs[lk + 1][lr] = bv.y;
        Bs[lk + 2][lr] = bv.z; Bs[lk + 3][lr] = bv.w;
        __syncthreads();
#pragma unroll
        for (int k = 0; k < 8; k++) {
            float a[8], bb[8];
            *(float4*)&a[0]  = *(const float4*)&As[k][m0];
            *(float4*)&a[4]  = *(const float4*)&As[k][m0 + 4];
            *(float4*)&bb[0] = *(const float4*)&Bs[k][n0];
            *(float4*)&bb[4] = *(const float4*)&Bs[k][n0 + 4];
#pragma unroll
            for (int i = 0; i < 8; i++)
#pragma unroll
                for (int j = 0; j < 8; j++) acc[i][j] = fmaf(a[i], bb[j], acc[i][j]);
        }
        __syncthreads();
    }
#pragma unroll
    for (int j = 0; j < 8; j++) {
        const int h = hB + n0 + j;
        const float bh = bias[h];
        const size_t base = ((size_t)b * HH + h) * TT + tB + m0;
#pragma unroll
        for (int i = 0; i < 8; i += 4) {
            float4 dv = *(const float4*)(dec + base + i);
            float4 o;
            o.x = SCALE * (acc[i + 0][j] + bh + dv.x);
            o.y = SCALE * (acc[i + 1][j] + bh + dv.y);
            o.z = SCALE * (acc[i + 2][j] + bh + dv.z);
            o.w = SCALE * (acc[i + 3][j] + bh + dv.w);
            *(float4*)(out + base + i) = o;
        }
    }
}

extern "C" void kernel_launch(void* const* d_in, const int* in_sizes, int n_in,
                              void* d_out, int out_size)
{
    const float* dec  = (const float*)d_in[0];
    const float* emb  = (const float*)d_in[1];
    const float* enc  = (const float*)d_in[2];
    const float* enb  = (const float*)d_in[3];
    const float* Wh2e = (const float*)d_in[4];
    const float* bh2e = (const float*)d_in[5];
    const float* We2h = (const float*)d_in[6];
    const float* be2h = (const float*)d_in[7];
    float* a_out    = (float*)d_out;                 // [B,T,S]
    float* conv_out = a_out + (size_t)BB * TT * SS;  // [B,H,T]

    cudaFuncSetAttribute(gemm3x, cudaFuncAttributeMaxDynamicSharedMemorySize, GEMM_SMEM);

    float* Qp   = nullptr; cudaGetSymbolAddress((void**)&Qp,   g_Q);
    float* Ctxp = nullptr; cudaGetSymbolAddress((void**)&Ctxp, g_ctx);
    float* Vtp  = nullptr; cudaGetSymbolAddress((void**)&Vtp,  g_Vt);

    k0_transpose<<<dim3(SS / 32, EE / 32, BB), dim3(32, 8)>>>(enb, Vtp);
    k1_q<<<dim3(EE / 128, TT / 128, BB), 256>>>(dec, emb, Wh2e, bh2e);

    // K2: energy = Q @ K^T -> a_out (raw)
    gemm3x<<<dim3(SS / 128, TT / 128, BB), 256, GEMM_SMEM>>>(
        Qp, EE, (size_t)TT * EE,
        enc, EE, (size_t)SS * EE,
        a_out, SS, (size_t)TT * SS,
        EE);

    k3_softmax<<<BB * TT, 256>>>(a_out);

    // K4: ctx = a @ V (V transposed to K-major)
    gemm3x<<<dim3(EE / 128, TT / 128, BB), 256, GEMM_SMEM>>>(
        a_out, SS, (size_t)TT * SS,
        Vtp, SS, (size_t)EE * SS,
        Ctxp, EE, (size_t)TT * EE,
        SS);

    k5_out<<<dim3(HH / 128, TT / 128, BB), 256>>>(dec, We2h, be2h, conv_out);
}

// round 6
// speedup vs baseline: 1.6921x; 1.6921x over previous
#include <cuda_runtime.h>
#include <cuda_fp16.h>
#include <cstdint>

#define BB 8
#define HH 512
#define EE 256
#define TT 2048
#define SS 2048
#define SCALE 0.8366600265340756f  // sqrt(0.7)

// ---- fp16 hi/lo scratch (device globals; no allocation in kernel_launch) ----
__device__ __half g_QH[BB * TT * EE],  g_QL[BB * TT * EE];
__device__ __half g_aH[(size_t)BB * TT * SS], g_aL[(size_t)BB * TT * SS];
__device__ __half g_cH[BB * TT * EE],  g_cL[BB * TT * EE];
__device__ __half g_VtH[BB * EE * SS], g_VtL[BB * EE * SS];
__device__ __half g_dtH[BB * TT * HH], g_dtL[BB * TT * HH];
__device__ __half g_KH[BB * SS * EE],  g_KL[BB * SS * EE];
__device__ __half g_WqH[EE * HH], g_WqL[EE * HH];
__device__ __half g_WoH[HH * EE], g_WoL[HH * EE];

__device__ __forceinline__ uint32_t smem_u32(const void* p) {
    uint32_t a;
    asm("{ .reg .u64 t; cvta.to.shared.u64 t, %1; cvt.u32.u64 %0, t; }" : "=r"(a) : "l"(p));
    return a;
}
#define CPA16(dst, src) \
    asm volatile("cp.async.ca.shared.global [%0], [%1], 16;" :: "r"(dst), "l"(src))
#define CPA_COMMIT() asm volatile("cp.async.commit_group;" ::: "memory")
#define CPA_WAIT(n)  asm volatile("cp.async.wait_group %0;" :: "n"(n) : "memory")
#define LDM4(r0, r1, r2, r3, addr)                                            \
    asm volatile("ldmatrix.sync.aligned.m8n8.x4.shared.b16 {%0,%1,%2,%3}, [%4];" \
        : "=r"(r0), "=r"(r1), "=r"(r2), "=r"(r3) : "r"(addr))
#define MMA16(c, a, b)                                                        \
    asm volatile("mma.sync.aligned.m16n8k16.row.col.f32.f16.f16.f32 "         \
        "{%0,%1,%2,%3},{%4,%5,%6,%7},{%8,%9},{%0,%1,%2,%3};"                  \
        : "+f"((c)[0]), "+f"((c)[1]), "+f"((c)[2]), "+f"((c)[3])              \
        : "r"((a)[0]), "r"((a)[1]), "r"((a)[2]), "r"((a)[3]),                 \
          "r"((b)[0]), "r"((b)[1]))

// ==================== fp16 3-term split GEMM ====================
// C[m,n] = sum_k A[m,k]*B[n,k], A/B given as hi+lo fp16 K-major arrays.
// acc = Ah*Bh + Ah*Bl + Al*Bh (fp32 accumulate).
// 256 thr = 8 warps (2x4), warp tile 64x32, BK=32, cp.async double-buffered.
// SMEM per stage (pitch 40 halves = 80B rows): 4 tiles x 128x40x2B = 40960B.
#define STAGE_B 40960
#define GEMMH_SMEM (2 * STAGE_B)

__device__ __forceinline__ void load_tiles(
    uint32_t smb, int st,
    const __half* Ah, const __half* Al, int lda,
    const __half* Bh, const __half* Bl, int ldb,
    int k0, int tid)
{
    const int row = tid >> 1;
    const int hq  = (tid & 1) * 16;  // halves offset within 32-half row
    const uint32_t d0 = smb + (uint32_t)st * STAGE_B + (uint32_t)row * 80u
                        + (uint32_t)(tid & 1) * 32u;
    const size_t sa = (size_t)row * lda + k0 + hq;
    const size_t sb = (size_t)row * ldb + k0 + hq;
    CPA16(d0 +     0, Ah + sa); CPA16(d0 +    16, Ah + sa + 8);
    CPA16(d0 + 10240, Al + sa); CPA16(d0 + 10256, Al + sa + 8);
    CPA16(d0 + 20480, Bh + sb); CPA16(d0 + 20496, Bh + sb + 8);
    CPA16(d0 + 30720, Bl + sb); CPA16(d0 + 30736, Bl + sb + 8);
}

__global__ void __launch_bounds__(256, 2) gemmh(
    const __half* __restrict__ AH, const __half* __restrict__ AL, int lda, size_t sA,
    const __half* __restrict__ BH, const __half* __restrict__ BL, int ldb, size_t sB,
    float* __restrict__ C, __half* __restrict__ CH, __half* __restrict__ CL,
    int ldc, size_t sC, int K, int mode,
    const float* __restrict__ bias,
    const float* __restrict__ aux, int ldaux, size_t saux)
{
    extern __shared__ __align__(16) char smraw[];
    const uint32_t smb = smem_u32(smraw);

    const int tid  = threadIdx.x;
    const int lane = tid & 31;
    const int wid  = tid >> 5;
    const int mB   = (wid >> 2) * 64;
    const int nB   = (wid & 3) * 32;
    const int g    = lane >> 2;
    const int tg   = lane & 3;
    const int l15  = lane & 15;
    const int lhi  = lane >> 4;

    const uint32_t aoff = (uint32_t)((mB + l15) * 80 + lhi * 16);
    const uint32_t boff = (uint32_t)((nB + l15) * 80 + lhi * 16);

    const int bz = blockIdx.z;
    const __half* Ah = AH + bz * sA + (size_t)(blockIdx.y * 128) * lda;
    const __half* Al = AL + bz * sA + (size_t)(blockIdx.y * 128) * lda;
    const __half* Bh = BH + bz * sB + (size_t)(blockIdx.x * 128) * ldb;
    const __half* Bl = BL + bz * sB + (size_t)(blockIdx.x * 128) * ldb;

    const int NC = K >> 5;
    float acc[4][4][4] = {};

    load_tiles(smb, 0, Ah, Al, lda, Bh, Bl, ldb, 0, tid);
    CPA_COMMIT();

    for (int c = 0; c < NC; c++) {
        if (c + 1 < NC) {
            load_tiles(smb, (c + 1) & 1, Ah, Al, lda, Bh, Bl, ldb, (c + 1) << 5, tid);
            CPA_COMMIT();
            CPA_WAIT(1);
        } else {
            CPA_WAIT(0);
        }
        __syncthreads();

        const uint32_t sb = smb + (uint32_t)(c & 1) * STAGE_B;
#pragma unroll
        for (int ks = 0; ks < 2; ks++) {
            const uint32_t ko = (uint32_t)ks * 32;
            uint32_t ah[4][4], al[4][4], bh[4][2], bl[4][2];
#pragma unroll
            for (int mi = 0; mi < 4; mi++) {
                LDM4(ah[mi][0], ah[mi][1], ah[mi][2], ah[mi][3],
                     sb + aoff + (uint32_t)mi * 1280 + ko);
                LDM4(al[mi][0], al[mi][1], al[mi][2], al[mi][3],
                     sb + 10240 + aoff + (uint32_t)mi * 1280 + ko);
            }
#pragma unroll
            for (int nj = 0; nj < 2; nj++)
                LDM4(bh[2 * nj][0], bh[2 * nj + 1][0], bh[2 * nj][1], bh[2 * nj + 1][1],
                     sb + 20480 + boff + (uint32_t)nj * 1280 + ko);
#pragma unroll
            for (int mi = 0; mi < 4; mi++)
#pragma unroll
                for (int ni = 0; ni < 4; ni++) {
                    MMA16(acc[mi][ni], ah[mi], bh[ni]);
                    MMA16(acc[mi][ni], al[mi], bh[ni]);
                }
#pragma unroll
            for (int nj = 0; nj < 2; nj++)
                LDM4(bl[2 * nj][0], bl[2 * nj + 1][0], bl[2 * nj][1], bl[2 * nj + 1][1],
                     sb + 30720 + boff + (uint32_t)nj * 1280 + ko);
#pragma unroll
            for (int mi = 0; mi < 4; mi++)
#pragma unroll
                for (int ni = 0; ni < 4; ni++)
                    MMA16(acc[mi][ni], ah[mi], bl[ni]);
        }
        __syncthreads();
    }

    // ---- epilogue ----
    if (mode == 0) {
        // plain fp32 store (energy)
        float* Cb = C + bz * sC;
#pragma unroll
        for (int mi = 0; mi < 4; mi++) {
            const int r = blockIdx.y * 128 + mB + mi * 16 + g;
#pragma unroll
            for (int ni = 0; ni < 4; ni++) {
                const int cc = blockIdx.x * 128 + nB + ni * 8 + 2 * tg;
                float2 v0 = {acc[mi][ni][0], acc[mi][ni][1]};
                float2 v1 = {acc[mi][ni][2], acc[mi][ni][3]};
                *(float2*)(Cb + (size_t)r * ldc + cc) = v0;
                *(float2*)(Cb + (size_t)(r + 8) * ldc + cc) = v1;
            }
        }
    } else if (mode == 2) {
        // transposed fp32 store + bias + residual + scale (output projection)
        float* Cb = C + bz * sC;
        const float* Db = aux + bz * saux;
#pragma unroll
        for (int mi = 0; mi < 4; mi++) {
            const int r = blockIdx.y * 128 + mB + mi * 16 + g;
#pragma unroll
            for (int ni = 0; ni < 4; ni++) {
                const int cc = blockIdx.x * 128 + nB + ni * 8 + 2 * tg;
                const float b0 = bias[cc], b1 = bias[cc + 1];
                Cb[(size_t)cc * ldc + r] =
                    SCALE * (acc[mi][ni][0] + b0 + Db[(size_t)cc * ldaux + r]);
                Cb[(size_t)(cc + 1) * ldc + r] =
                    SCALE * (acc[mi][ni][1] + b1 + Db[(size_t)(cc + 1) * ldaux + r]);
                Cb[(size_t)cc * ldc + r + 8] =
                    SCALE * (acc[mi][ni][2] + b0 + Db[(size_t)cc * ldaux + r + 8]);
                Cb[(size_t)(cc + 1) * ldc + r + 8] =
                    SCALE * (acc[mi][ni][3] + b1 + Db[(size_t)(cc + 1) * ldaux + r + 8]);
            }
        }
    } else {
        // fp16 hi/lo store; mode 1 adds bias + emb + scale (Q projection)
        __half* CHb = CH + bz * sC;
        __half* CLb = CL + bz * sC;
#pragma unroll
        for (int mi = 0; mi < 4; mi++) {
            const int r = blockIdx.y * 128 + mB + mi * 16 + g;
#pragma unroll
            for (int ni = 0; ni < 4; ni++) {
                const int cc = blockIdx.x * 128 + nB + ni * 8 + 2 * tg;
                float q0 = acc[mi][ni][0], q1 = acc[mi][ni][1];
                float q2 = acc[mi][ni][2], q3 = acc[mi][ni][3];
                if (mode == 1) {
                    const float2 bi = *(const float2*)(bias + cc);
                    const float2 e0 = *(const float2*)(aux + bz * saux + (size_t)r * ldaux + cc);
                    const float2 e1 = *(const float2*)(aux + bz * saux + (size_t)(r + 8) * ldaux + cc);
                    q0 = SCALE * (q0 + bi.x + e0.x); q1 = SCALE * (q1 + bi.y + e0.y);
                    q2 = SCALE * (q2 + bi.x + e1.x); q3 = SCALE * (q3 + bi.y + e1.y);
                }
                __half2 h0 = __floats2half2_rn(q0, q1);
                float2 f0 = __half22float2(h0);
                __half2 l0 = __floats2half2_rn(q0 - f0.x, q1 - f0.y);
                __half2 h1 = __floats2half2_rn(q2, q3);
                float2 f1 = __half22float2(h1);
                __half2 l1 = __floats2half2_rn(q2 - f1.x, q3 - f1.y);
                *(__half2*)(CHb + (size_t)r * ldc + cc) = h0;
                *(__half2*)(CLb + (size_t)r * ldc + cc) = l0;
                *(__half2*)(CHb + (size_t)(r + 8) * ldc + cc) = h1;
                *(__half2*)(CLb + (size_t)(r + 8) * ldc + cc) = l1;
            }
        }
    }
}

// ==================== prep: elementwise fp32 -> hi/lo fp16 ====================
__global__ void __launch_bounds__(256) split_plain(
    const float* __restrict__ s, __half* __restrict__ dH, __half* __restrict__ dL)
{
    const size_t i4 = ((size_t)blockIdx.x * 256 + threadIdx.x) * 4;
    float4 v = *(const float4*)(s + i4);
    __half2 h01 = __floats2half2_rn(v.x, v.y);
    __half2 h23 = __floats2half2_rn(v.z, v.w);
    float2 f01 = __half22float2(h01);
    float2 f23 = __half22float2(h23);
    __half2 l01 = __floats2half2_rn(v.x - f01.x, v.y - f01.y);
    __half2 l23 = __floats2half2_rn(v.z - f23.x, v.w - f23.y);
    ((__half2*)dH)[i4 >> 1] = h01; ((__half2*)dH)[(i4 >> 1) + 1] = h23;
    ((__half2*)dL)[i4 >> 1] = l01; ((__half2*)dL)[(i4 >> 1) + 1] = l23;
}

// ==================== prep: transpose + split: src[R][Cc] -> dst[Cc][R] ====================
__global__ void __launch_bounds__(256) transpose_split(
    const float* __restrict__ src, __half* __restrict__ dH, __half* __restrict__ dL,
    int R, int Cc)
{
    __shared__ float t[32][33];
    const size_t base = (size_t)blockIdx.z * R * Cc;
    const int r0 = blockIdx.x * 32, c0 = blockIdx.y * 32;
    const int x = threadIdx.x, y = threadIdx.y;
#pragma unroll
    for (int i = 0; i < 32; i += 8)
        t[y + i][x] = src[base + (size_t)(r0 + y + i) * Cc + c0 + x];
    __syncthreads();
#pragma unroll
    for (int i = 0; i < 32; i += 8) {
        const float v = t[x][y + i];
        const __half h = __float2half_rn(v);
        const size_t idx = base + (size_t)(c0 + y + i) * R + r0 + x;
        dH[idx] = h;
        dL[idx] = __float2half_rn(v - __half2float(h));
    }
}

// ==================== softmax (in-place fp32 + fp16 hi/lo out) ====================
__global__ void __launch_bounds__(256) k3_softmax(
    float* __restrict__ a, __half* __restrict__ aH, __half* __restrict__ aL)
{
    const size_t row = blockIdx.x;
    float* p = a + row * SS;
    const int tid = threadIdx.x;
    float v[8];
#pragma unroll
    for (int i = 0; i < 8; i++) v[i] = p[tid + (i << 8)];
    float m = v[0];
#pragma unroll
    for (int i = 1; i < 8; i++) m = fmaxf(m, v[i]);
#pragma unroll
    for (int o = 16; o > 0; o >>= 1) m = fmaxf(m, __shfl_xor_sync(0xffffffffu, m, o));
    __shared__ float red[8];
    if ((tid & 31) == 0) red[tid >> 5] = m;
    __syncthreads();
    float M = red[0];
#pragma unroll
    for (int i = 1; i < 8; i++) M = fmaxf(M, red[i]);
    float s = 0.f;
#pragma unroll
    for (int i = 0; i < 8; i++) { v[i] = __expf(v[i] - M); s += v[i]; }
#pragma unroll
    for (int o = 16; o > 0; o >>= 1) s += __shfl_xor_sync(0xffffffffu, s, o);
    __syncthreads();
    if ((tid & 31) == 0) red[tid >> 5] = s;
    __syncthreads();
    float Z = 0.f;
#pragma unroll
    for (int i = 0; i < 8; i++) Z += red[i];
    const float inv = 1.f / Z;
#pragma unroll
    for (int i = 0; i < 8; i++) {
        const float q = v[i] * inv;
        const size_t idx = row * SS + tid + (i << 8);
        p[tid + (i << 8)] = q;
        const __half h = __float2half_rn(q);
        aH[idx] = h;
        aL[idx] = __float2half_rn(q - __half2float(h));
    }
}

extern "C" void kernel_launch(void* const* d_in, const int* in_sizes, int n_in,
                              void* d_out, int out_size)
{
    const float* dec  = (const float*)d_in[0];
    const float* emb  = (const float*)d_in[1];
    const float* enc  = (const float*)d_in[2];
    const float* enb  = (const float*)d_in[3];
    const float* Wh2e = (const float*)d_in[4];
    const float* bh2e = (const float*)d_in[5];
    const float* We2h = (const float*)d_in[6];
    const float* be2h = (const float*)d_in[7];
    float* a_out    = (float*)d_out;                 // [B,T,S]
    float* conv_out = a_out + (size_t)BB * TT * SS;  // [B,H,T]

    cudaFuncSetAttribute(gemmh, cudaFuncAttributeMaxDynamicSharedMemorySize, GEMMH_SMEM);

#define SYM(p, s) __half* p = nullptr; cudaGetSymbolAddress((void**)&p, s)
    SYM(QH, g_QH);  SYM(QL, g_QL);
    SYM(aH, g_aH);  SYM(aL, g_aL);
    SYM(cH, g_cH);  SYM(cL, g_cL);
    SYM(VtH, g_VtH); SYM(VtL, g_VtL);
    SYM(dtH, g_dtH); SYM(dtL, g_dtL);
    SYM(KHp, g_KH); SYM(KLp, g_KL);
    SYM(WqH, g_WqH); SYM(WqL, g_WqL);
    SYM(WoH, g_WoH); SYM(WoL, g_WoL);
#undef SYM

    // prep: splits + transposes
    split_plain<<<BB * SS * EE / 1024, 256>>>(enc, KHp, KLp);
    split_plain<<<EE * HH / 1024, 256>>>(Wh2e, WqH, WqL);
    split_plain<<<HH * EE / 1024, 256>>>(We2h, WoH, WoL);
    transpose_split<<<dim3(SS / 32, EE / 32, BB), dim3(32, 8)>>>(enb, VtH, VtL, SS, EE);
    transpose_split<<<dim3(HH / 32, TT / 32, BB), dim3(32, 8)>>>(dec, dtH, dtL, HH, TT);

    // K1: Q = SCALE*(dec^T @ Wq^T + bias + emb) -> fp16 hi/lo
    gemmh<<<dim3(EE / 128, TT / 128, BB), 256, GEMMH_SMEM>>>(
        dtH, dtL, HH, (size_t)TT * HH,
        WqH, WqL, HH, 0,
        nullptr, QH, QL, EE, (size_t)TT * EE,
        HH, 1, bh2e, emb, EE, (size_t)TT * EE);

    // K2: energy = Q @ K^T -> fp32 a_out (raw)
    gemmh<<<dim3(SS / 128, TT / 128, BB), 256, GEMMH_SMEM>>>(
        QH, QL, EE, (size_t)TT * EE,
        KHp, KLp, EE, (size_t)SS * EE,
        a_out, nullptr, nullptr, SS, (size_t)TT * SS,
        EE, 0, nullptr, nullptr, 0, 0);

    k3_softmax<<<BB * TT, 256>>>(a_out, aH, aL);

    // K4: ctx = a @ V -> fp16 hi/lo
    gemmh<<<dim3(EE / 128, TT / 128, BB), 256, GEMMH_SMEM>>>(
        aH, aL, SS, (size_t)TT * SS,
        VtH, VtL, SS, (size_t)EE * SS,
        nullptr, cH, cL, EE, (size_t)TT * EE,
        SS, 3, nullptr, nullptr, 0, 0);

    // K5: out = SCALE*(ctx @ Wo^T + bias + dec), transposed store
    gemmh<<<dim3(HH / 128, TT / 128, BB), 256, GEMMH_SMEM>>>(
        cH, cL, EE, (size_t)TT * EE,
        WoH, WoL, EE, 0,
        conv_out, nullptr, nullptr, TT, (size_t)HH * TT,
        EE, 2, be2h, dec, TT, (size_t)HH * TT);
}

// round 7
// speedup vs baseline: 1.9953x; 1.1792x over previous
#include <cuda_runtime.h>
#include <cuda_fp16.h>
#include <cstdint>

#define BB 8
#define HH 512
#define EE 256
#define TT 2048
#define SS 2048
#define SCALE 0.8366600265340756f  // sqrt(0.7)

// ---- fp16 hi/lo scratch (device globals; no allocation in kernel_launch) ----
__device__ __half g_QH[BB * TT * EE],  g_QL[BB * TT * EE];
__device__ __half g_aH[(size_t)BB * TT * SS];
__device__ __half g_cH[BB * TT * EE];
__device__ __half g_VtH[BB * EE * SS], g_VtL[BB * EE * SS];
__device__ __half g_dtH[BB * TT * HH], g_dtL[BB * TT * HH];
__device__ __half g_KH[BB * SS * EE],  g_KL[BB * SS * EE];
__device__ __half g_WqH[EE * HH], g_WqL[EE * HH];
__device__ __half g_WoH[HH * EE], g_WoL[HH * EE];

__device__ __forceinline__ uint32_t smem_u32(const void* p) {
    uint32_t a;
    asm("{ .reg .u64 t; cvta.to.shared.u64 t, %1; cvt.u32.u64 %0, t; }" : "=r"(a) : "l"(p));
    return a;
}
#define CPA16(dst, src) \
    asm volatile("cp.async.ca.shared.global [%0], [%1], 16;" :: "r"(dst), "l"(src))
#define CPA_COMMIT() asm volatile("cp.async.commit_group;" ::: "memory")
#define CPA_WAIT(n)  asm volatile("cp.async.wait_group %0;" :: "n"(n) : "memory")
#define LDM4(r0, r1, r2, r3, addr)                                            \
    asm volatile("ldmatrix.sync.aligned.m8n8.x4.shared.b16 {%0,%1,%2,%3}, [%4];" \
        : "=r"(r0), "=r"(r1), "=r"(r2), "=r"(r3) : "r"(addr))
#define MMA16(c, a, b)                                                        \
    asm volatile("mma.sync.aligned.m16n8k16.row.col.f32.f16.f16.f32 "         \
        "{%0,%1,%2,%3},{%4,%5,%6,%7},{%8,%9},{%0,%1,%2,%3};"                  \
        : "+f"((c)[0]), "+f"((c)[1]), "+f"((c)[2]), "+f"((c)[3])              \
        : "r"((a)[0]), "r"((a)[1]), "r"((a)[2]), "r"((a)[3]),                 \
          "r"((b)[0]), "r"((b)[1]))

// ==================== fp16 split GEMM ====================
// C[m,n] = sum_k A[m,k]*B[n,k]; A/B K-major fp16 hi(+lo).
// 3-term (TWOA=false): Ah*Bh + Ah*Bl + Al*Bh.   2-term (TWOA=true): Ah*Bh + Ah*Bl.
// 256 thr = 8 warps (2x4), warp tile 64x32, BK=32, cp.async double-buffered.
// SMEM stage (pitch 40 halves = 80B): Ah@0, Al@10240, Bh@20480, Bl@30720.
#define STAGE_B 40960
#define GEMMH_SMEM (2 * STAGE_B)

template <bool TWOA>
__device__ __forceinline__ void load_tiles(
    uint32_t smb, int st,
    const __half* Ah, const __half* Al, int lda,
    const __half* Bh, const __half* Bl, int ldb,
    int k0, int tid)
{
    const int row = tid >> 1;
    const int hq  = (tid & 1) * 16;
    const uint32_t d0 = smb + (uint32_t)st * STAGE_B + (uint32_t)row * 80u
                        + (uint32_t)(tid & 1) * 32u;
    const size_t sa = (size_t)row * lda + k0 + hq;
    const size_t sb = (size_t)row * ldb + k0 + hq;
    CPA16(d0 +     0, Ah + sa); CPA16(d0 +    16, Ah + sa + 8);
    if (!TWOA) {
        CPA16(d0 + 10240, Al + sa); CPA16(d0 + 10256, Al + sa + 8);
    }
    CPA16(d0 + 20480, Bh + sb); CPA16(d0 + 20496, Bh + sb + 8);
    CPA16(d0 + 30720, Bl + sb); CPA16(d0 + 30736, Bl + sb + 8);
}

template <bool TWOA>
__global__ void __launch_bounds__(256, 2) gemmh(
    const __half* __restrict__ AH, const __half* __restrict__ AL, int lda, size_t sA,
    const __half* __restrict__ BH, const __half* __restrict__ BL, int ldb, size_t sB,
    float* __restrict__ C, __half* __restrict__ CH, __half* __restrict__ CL,
    int ldc, size_t sC, int K, int mode,
    const float* __restrict__ bias,
    const float* __restrict__ aux, int ldaux, size_t saux)
{
    extern __shared__ __align__(16) char smraw[];
    const uint32_t smb = smem_u32(smraw);

    const int tid  = threadIdx.x;
    const int lane = tid & 31;
    const int wid  = tid >> 5;
    const int mB   = (wid >> 2) * 64;
    const int nB   = (wid & 3) * 32;
    const int g    = lane >> 2;
    const int tg   = lane & 3;
    const int l15  = lane & 15;
    const int lhi  = lane >> 4;

    const uint32_t aoff = (uint32_t)((mB + l15) * 80 + lhi * 16);
    const uint32_t boff = (uint32_t)((nB + l15) * 80 + lhi * 16);

    const int bz = blockIdx.z;
    const __half* Ah = AH + bz * sA + (size_t)(blockIdx.y * 128) * lda;
    const __half* Al = TWOA ? nullptr : AL + bz * sA + (size_t)(blockIdx.y * 128) * lda;
    const __half* Bh = BH + bz * sB + (size_t)(blockIdx.x * 128) * ldb;
    const __half* Bl = BL + bz * sB + (size_t)(blockIdx.x * 128) * ldb;

    const int NC = K >> 5;
    float acc[4][4][4] = {};

    load_tiles<TWOA>(smb, 0, Ah, Al, lda, Bh, Bl, ldb, 0, tid);
    CPA_COMMIT();

    for (int c = 0; c < NC; c++) {
        if (c + 1 < NC) {
            load_tiles<TWOA>(smb, (c + 1) & 1, Ah, Al, lda, Bh, Bl, ldb, (c + 1) << 5, tid);
            CPA_COMMIT();
            CPA_WAIT(1);
        } else {
            CPA_WAIT(0);
        }
        __syncthreads();

        const uint32_t sb = smb + (uint32_t)(c & 1) * STAGE_B;
#pragma unroll
        for (int ks = 0; ks < 2; ks++) {
            const uint32_t ko = (uint32_t)ks * 32;
            uint32_t ah[4][4], al[4][4], bh[4][2], bl[4][2];
#pragma unroll
            for (int mi = 0; mi < 4; mi++) {
                LDM4(ah[mi][0], ah[mi][1], ah[mi][2], ah[mi][3],
                     sb + aoff + (uint32_t)mi * 1280 + ko);
                if (!TWOA)
                    LDM4(al[mi][0], al[mi][1], al[mi][2], al[mi][3],
                         sb + 10240 + aoff + (uint32_t)mi * 1280 + ko);
            }
#pragma unroll
            for (int nj = 0; nj < 2; nj++)
                LDM4(bh[2 * nj][0], bh[2 * nj + 1][0], bh[2 * nj][1], bh[2 * nj + 1][1],
                     sb + 20480 + boff + (uint32_t)nj * 1280 + ko);
#pragma unroll
            for (int mi = 0; mi < 4; mi++)
#pragma unroll
                for (int ni = 0; ni < 4; ni++) {
                    MMA16(acc[mi][ni], ah[mi], bh[ni]);
                    if (!TWOA) MMA16(acc[mi][ni], al[mi], bh[ni]);
                }
#pragma unroll
            for (int nj = 0; nj < 2; nj++)
                LDM4(bl[2 * nj][0], bl[2 * nj + 1][0], bl[2 * nj][1], bl[2 * nj + 1][1],
                     sb + 30720 + boff + (uint32_t)nj * 1280 + ko);
#pragma unroll
            for (int mi = 0; mi < 4; mi++)
#pragma unroll
                for (int ni = 0; ni < 4; ni++)
                    MMA16(acc[mi][ni], ah[mi], bl[ni]);
        }
        __syncthreads();
    }

    // ---- epilogue ----
    if (mode == 0) {
        // plain fp32 store (energy)
        float* Cb = C + bz * sC;
#pragma unroll
        for (int mi = 0; mi < 4; mi++) {
            const int r = blockIdx.y * 128 + mB + mi * 16 + g;
#pragma unroll
            for (int ni = 0; ni < 4; ni++) {
                const int cc = blockIdx.x * 128 + nB + ni * 8 + 2 * tg;
                float2 v0 = {acc[mi][ni][0], acc[mi][ni][1]};
                float2 v1 = {acc[mi][ni][2], acc[mi][ni][3]};
                *(float2*)(Cb + (size_t)r * ldc + cc) = v0;
                *(float2*)(Cb + (size_t)(r + 8) * ldc + cc) = v1;
            }
        }
    } else if (mode == 2) {
        // transposed fp32 store + bias + residual + scale (output projection)
        float* Cb = C + bz * sC;
        const float* Db = aux + bz * saux;
#pragma unroll
        for (int mi = 0; mi < 4; mi++) {
            const int r = blockIdx.y * 128 + mB + mi * 16 + g;
#pragma unroll
            for (int ni = 0; ni < 4; ni++) {
                const int cc = blockIdx.x * 128 + nB + ni * 8 + 2 * tg;
                const float b0 = bias[cc], b1 = bias[cc + 1];
                Cb[(size_t)cc * ldc + r] =
                    SCALE * (acc[mi][ni][0] + b0 + Db[(size_t)cc * ldaux + r]);
                Cb[(size_t)(cc + 1) * ldc + r] =
                    SCALE * (acc[mi][ni][1] + b1 + Db[(size_t)(cc + 1) * ldaux + r]);
                Cb[(size_t)cc * ldc + r + 8] =
                    SCALE * (acc[mi][ni][2] + b0 + Db[(size_t)cc * ldaux + r + 8]);
                Cb[(size_t)(cc + 1) * ldc + r + 8] =
                    SCALE * (acc[mi][ni][3] + b1 + Db[(size_t)(cc + 1) * ldaux + r + 8]);
            }
        }
    } else if (mode == 1) {
        // fp16 hi/lo store + bias + emb + scale (Q projection)
        __half* CHb = CH + bz * sC;
        __half* CLb = CL + bz * sC;
#pragma unroll
        for (int mi = 0; mi < 4; mi++) {
            const int r = blockIdx.y * 128 + mB + mi * 16 + g;
#pragma unroll
            for (int ni = 0; ni < 4; ni++) {
                const int cc = blockIdx.x * 128 + nB + ni * 8 + 2 * tg;
                const float2 bi = *(const float2*)(bias + cc);
                const float2 e0 = *(const float2*)(aux + bz * saux + (size_t)r * ldaux + cc);
                const float2 e1 = *(const float2*)(aux + bz * saux + (size_t)(r + 8) * ldaux + cc);
                float q0 = SCALE * (acc[mi][ni][0] + bi.x + e0.x);
                float q1 = SCALE * (acc[mi][ni][1] + bi.y + e0.y);
                float q2 = SCALE * (acc[mi][ni][2] + bi.x + e1.x);
                float q3 = SCALE * (acc[mi][ni][3] + bi.y + e1.y);
                __half2 h0 = __floats2half2_rn(q0, q1);
                float2 f0 = __half22float2(h0);
                __half2 l0 = __floats2half2_rn(q0 - f0.x, q1 - f0.y);
                __half2 h1 = __floats2half2_rn(q2, q3);
                float2 f1 = __half22float2(h1);
                __half2 l1 = __floats2half2_rn(q2 - f1.x, q3 - f1.y);
                *(__half2*)(CHb + (size_t)r * ldc + cc) = h0;
                *(__half2*)(CLb + (size_t)r * ldc + cc) = l0;
                *(__half2*)(CHb + (size_t)(r + 8) * ldc + cc) = h1;
                *(__half2*)(CLb + (size_t)(r + 8) * ldc + cc) = l1;
            }
        }
    } else {
        // mode 3: fp16 hi-only store (context)
        __half* CHb = CH + bz * sC;
#pragma unroll
        for (int mi = 0; mi < 4; mi++) {
            const int r = blockIdx.y * 128 + mB + mi * 16 + g;
#pragma unroll
            for (int ni = 0; ni < 4; ni++) {
                const int cc = blockIdx.x * 128 + nB + ni * 8 + 2 * tg;
                *(__half2*)(CHb + (size_t)r * ldc + cc) =
                    __floats2half2_rn(acc[mi][ni][0], acc[mi][ni][1]);
                *(__half2*)(CHb + (size_t)(r + 8) * ldc + cc) =
                    __floats2half2_rn(acc[mi][ni][2], acc[mi][ni][3]);
            }
        }
    }
}

// ==================== prep: elementwise fp32 -> hi/lo fp16 ====================
__global__ void __launch_bounds__(256) split_plain(
    const float* __restrict__ s, __half* __restrict__ dH, __half* __restrict__ dL)
{
    const size_t i4 = ((size_t)blockIdx.x * 256 + threadIdx.x) * 4;
    float4 v = *(const float4*)(s + i4);
    __half2 h01 = __floats2half2_rn(v.x, v.y);
    __half2 h23 = __floats2half2_rn(v.z, v.w);
    float2 f01 = __half22float2(h01);
    float2 f23 = __half22float2(h23);
    __half2 l01 = __floats2half2_rn(v.x - f01.x, v.y - f01.y);
    __half2 l23 = __floats2half2_rn(v.z - f23.x, v.w - f23.y);
    ((__half2*)dH)[i4 >> 1] = h01; ((__half2*)dH)[(i4 >> 1) + 1] = h23;
    ((__half2*)dL)[i4 >> 1] = l01; ((__half2*)dL)[(i4 >> 1) + 1] = l23;
}

// ==================== prep: transpose + split: src[R][Cc] -> dst[Cc][R] ====================
__global__ void __launch_bounds__(256) transpose_split(
    const float* __restrict__ src, __half* __restrict__ dH, __half* __restrict__ dL,
    int R, int Cc)
{
    __shared__ float t[32][33];
    const size_t base = (size_t)blockIdx.z * R * Cc;
    const int r0 = blockIdx.x * 32, c0 = blockIdx.y * 32;
    const int x = threadIdx.x, y = threadIdx.y;
#pragma unroll
    for (int i = 0; i < 32; i += 8)
        t[y + i][x] = src[base + (size_t)(r0 + y + i) * Cc + c0 + x];
    __syncthreads();
#pragma unroll
    for (int i = 0; i < 32; i += 8) {
        const float v = t[x][y + i];
        const __half h = __float2half_rn(v);
        const size_t idx = base + (size_t)(c0 + y + i) * R + r0 + x;
        dH[idx] = h;
        dL[idx] = __float2half_rn(v - __half2float(h));
    }
}

// ==================== softmax (fp32 out + fp16 hi out) ====================
__global__ void __launch_bounds__(256) k3_softmax(
    float* __restrict__ a, __half* __restrict__ aH)
{
    const size_t row = blockIdx.x;
    float* p = a + row * SS;
    const int tid = threadIdx.x;
    float v[8];
#pragma unroll
    for (int i = 0; i < 8; i++) v[i] = p[tid + (i << 8)];
    float m = v[0];
#pragma unroll
    for (int i = 1; i < 8; i++) m = fmaxf(m, v[i]);
#pragma unroll
    for (int o = 16; o > 0; o >>= 1) m = fmaxf(m, __shfl_xor_sync(0xffffffffu, m, o));
    __shared__ float red[8];
    if ((tid & 31) == 0) red[tid >> 5] = m;
    __syncthreads();
    float M = red[0];
#pragma unroll
    for (int i = 1; i < 8; i++) M = fmaxf(M, red[i]);
    float s = 0.f;
#pragma unroll
    for (int i = 0; i < 8; i++) { v[i] = __expf(v[i] - M); s += v[i]; }
#pragma unroll
    for (int o = 16; o > 0; o >>= 1) s += __shfl_xor_sync(0xffffffffu, s, o);
    __syncthreads();
    if ((tid & 31) == 0) red[tid >> 5] = s;
    __syncthreads();
    float Z = 0.f;
#pragma unroll
    for (int i = 0; i < 8; i++) Z += red[i];
    const float inv = 1.f / Z;
#pragma unroll
    for (int i = 0; i < 8; i++) {
        const float q = v[i] * inv;
        p[tid + (i << 8)] = q;
        aH[row * SS + tid + (i << 8)] = __float2half_rn(q);
    }
}

extern "C" void kernel_launch(void* const* d_in, const int* in_sizes, int n_in,
                              void* d_out, int out_size)
{
    const float* dec  = (const float*)d_in[0];
    const float* emb  = (const float*)d_in[1];
    const float* enc  = (const float*)d_in[2];
    const float* enb  = (const float*)d_in[3];
    const float* Wh2e = (const float*)d_in[4];
    const float* bh2e = (const float*)d_in[5];
    const float* We2h = (const float*)d_in[6];
    const float* be2h = (const float*)d_in[7];
    float* a_out    = (float*)d_out;                 // [B,T,S]
    float* conv_out = a_out + (size_t)BB * TT * SS;  // [B,H,T]

    cudaFuncSetAttribute(gemmh<false>, cudaFuncAttributeMaxDynamicSharedMemorySize, GEMMH_SMEM);
    cudaFuncSetAttribute(gemmh<true>,  cudaFuncAttributeMaxDynamicSharedMemorySize, GEMMH_SMEM);

#define SYM(p, s) __half* p = nullptr; cudaGetSymbolAddress((void**)&p, s)
    SYM(QH, g_QH);  SYM(QL, g_QL);
    SYM(aH, g_aH);
    SYM(cH, g_cH);
    SYM(VtH, g_VtH); SYM(VtL, g_VtL);
    SYM(dtH, g_dtH); SYM(dtL, g_dtL);
    SYM(KHp, g_KH); SYM(KLp, g_KL);
    SYM(WqH, g_WqH); SYM(WqL, g_WqL);
    SYM(WoH, g_WoH); SYM(WoL, g_WoL);
#undef SYM

    // prep: splits + transposes
    split_plain<<<BB * SS * EE / 1024, 256>>>(enc, KHp, KLp);
    split_plain<<<EE * HH / 1024, 256>>>(Wh2e, WqH, WqL);
    split_plain<<<HH * EE / 1024, 256>>>(We2h, WoH, WoL);
    transpose_split<<<dim3(SS / 32, EE / 32, BB), dim3(32, 8)>>>(enb, VtH, VtL, SS, EE);
    transpose_split<<<dim3(HH / 32, TT / 32, BB), dim3(32, 8)>>>(dec, dtH, dtL, HH, TT);

    // K1 (3-term): Q = SCALE*(dec^T @ Wq^T + bias + emb) -> fp16 hi/lo
    gemmh<false><<<dim3(EE / 128, TT / 128, BB), 256, GEMMH_SMEM>>>(
        dtH, dtL, HH, (size_t)TT * HH,
        WqH, WqL, HH, 0,
        nullptr, QH, QL, EE, (size_t)TT * EE,
        HH, 1, bh2e, emb, EE, (size_t)TT * EE);

    // K2 (3-term): energy = Q @ K^T -> fp32 a_out (raw)
    gemmh<false><<<dim3(SS / 128, TT / 128, BB), 256, GEMMH_SMEM>>>(
        QH, QL, EE, (size_t)TT * EE,
        KHp, KLp, EE, (size_t)SS * EE,
        a_out, nullptr, nullptr, SS, (size_t)TT * SS,
        EE, 0, nullptr, nullptr, 0, 0);

    k3_softmax<<<BB * TT, 256>>>(a_out, aH);

    // K4 (2-term): ctx = a @ V -> fp16 hi only
    gemmh<true><<<dim3(EE / 128, TT / 128, BB), 256, GEMMH_SMEM>>>(
        aH, nullptr, SS, (size_t)TT * SS,
        VtH, VtL, SS, (size_t)EE * SS,
        nullptr, cH, nullptr, EE, (size_t)TT * EE,
        SS, 3, nullptr, nullptr, 0, 0);

    // K5 (2-term): out = SCALE*(ctx @ Wo^T + bias + dec), transposed store
    gemmh<true><<<dim3(HH / 128, TT / 128, BB), 256, GEMMH_SMEM>>>(
        cH, nullptr, EE, (size_t)TT * EE,
        WoH, WoL, EE, 0,
        conv_out, nullptr, nullptr, TT, (size_t)HH * TT,
        EE, 2, be2h, dec, TT, (size_t)HH * TT);
}